// round 7
// baseline (speedup 1.0000x reference)
#include <cuda_runtime.h>

#define D      1024
#define BATCH  64
#define KSPLIT 32
#define KSLICE (D / KSPLIT)      // 32
#define NTILES (D / 64)          // 16
#define LOG2E  1.4426950408889634f
#define LN2    0.6931471805599453f

// ---------------- scratch (no allocations allowed) ----------------
__device__ __align__(16) float g_xl[BATCH * D];
__device__ __align__(16) float g_bl[BATCH * D];
__device__ __align__(16) float g_xs[BATCH * D];
__device__ __align__(16) float g_h1[BATCH * D];
__device__ __align__(16) float g_h2[BATCH * D];
__device__ __align__(16) float g_part[KSPLIT * BATCH * D];   // 8 MB
__device__ unsigned g_cnt[2][NTILES];

__device__ __forceinline__ float ex2f(float x) {
    float r;
    asm("ex2.approx.ftz.f32 %0, %1;" : "=f"(r) : "f"(x));
    return r;
}

__device__ __forceinline__ void ffma2(unsigned long long& acc,
                                      unsigned long long a,
                                      unsigned long long b) {
    asm("fma.rn.f32x2 %0, %1, %2, %3;" : "=l"(acc) : "l"(a), "l"(b), "l"(acc));
}

__device__ __forceinline__ unsigned long long dup2(float v) {
    unsigned long long r;
    asm("mov.b64 %0, {%1, %1};" : "=l"(r) : "f"(v));
    return r;
}

// ---------------- kernel 1: per-row bitonic sort + prefix-sum Bsum ----------------
__global__ void __launch_bounds__(D) sort_kernel(const float* __restrict__ x) {
    int row = blockIdx.x;
    int tid = threadIdx.x;
    __shared__ __align__(16) float sv[D];
    __shared__ float wsum[32];

    sv[tid] = x[row * D + tid];
    __syncthreads();

    for (int k = 2; k <= D; k <<= 1) {
        for (int j = k >> 1; j > 0; j >>= 1) {
            int ixj = tid ^ j;
            if (ixj > tid) {
                float a = sv[tid], b = sv[ixj];
                bool up = ((tid & k) == 0);
                if ((a > b) == up) { sv[tid] = b; sv[ixj] = a; }
            }
            __syncthreads();
        }
    }

    float v = sv[tid];
    int lane = tid & 31, wid = tid >> 5;
    float p = v;
#pragma unroll
    for (int off = 1; off < 32; off <<= 1) {
        float n = __shfl_up_sync(0xffffffffu, p, off);
        if (lane >= off) p += n;
    }
    if (lane == 31) wsum[wid] = p;
    __syncthreads();
    if (wid == 0) {
        float w = wsum[lane];
#pragma unroll
        for (int off = 1; off < 32; off <<= 1) {
            float n = __shfl_up_sync(0xffffffffu, w, off);
            if (lane >= off) w += n;
        }
        wsum[lane] = w;
    }
    __syncthreads();
    float S    = wsum[31];
    float pinc = p + (wid ? wsum[wid - 1] : 0.f);
    float bs   = (float)(2 * tid - D) * v + S - 2.f * (pinc - v);
    g_xl[row * D + tid] = v * LOG2E;
    g_bl[row * D + tid] = bs * LOG2E;
}

// ---------------- kernel 2: windowed soft-sort, unroll-4 ----------------
__global__ void __launch_bounds__(256) softsort_kernel() {
    int row = blockIdx.y;
    int i   = blockIdx.x * blockDim.x + threadIdx.x;
    __shared__ __align__(16) float sxl[D];
    __shared__ __align__(16) float sbl[D];
    ((float4*)sxl)[threadIdx.x] = ((const float4*)(g_xl + row * D))[threadIdx.x];
    ((float4*)sbl)[threadIdx.x] = ((const float4*)(g_bl + row * D))[threadIdx.x];
    __syncthreads();

    float c  = (float)(D - 1 - 2 * i);
    int   rm = D - 1 - i;
    float mx = fmaf(c, sxl[rm], -sbl[rm]);
    float num = sxl[rm], den = 1.f;
    const float T = 22.f;

    {
        int r = rm - 1;
        for (; r >= 3; r -= 4) {
            float t0 = fmaf(c, sxl[r],     -sbl[r])     - mx;
            float t1 = fmaf(c, sxl[r - 1], -sbl[r - 1]) - mx;
            float t2 = fmaf(c, sxl[r - 2], -sbl[r - 2]) - mx;
            float t3 = fmaf(c, sxl[r - 3], -sbl[r - 3]) - mx;
            float e0 = ex2f(t0), e1 = ex2f(t1), e2 = ex2f(t2), e3 = ex2f(t3);
            den += e0; num = fmaf(e0, sxl[r],     num);
            den += e1; num = fmaf(e1, sxl[r - 1], num);
            den += e2; num = fmaf(e2, sxl[r - 2], num);
            den += e3; num = fmaf(e3, sxl[r - 3], num);
            if (t3 < -T) { r = -1; break; }
        }
        for (; r >= 0; --r) {
            float t = fmaf(c, sxl[r], -sbl[r]) - mx;
            if (t < -T) break;
            float e = ex2f(t);
            den += e; num = fmaf(e, sxl[r], num);
        }
    }
    {
        int r = rm + 1;
        for (; r < D - 3; r += 4) {
            float t0 = fmaf(c, sxl[r],     -sbl[r])     - mx;
            float t1 = fmaf(c, sxl[r + 1], -sbl[r + 1]) - mx;
            float t2 = fmaf(c, sxl[r + 2], -sbl[r + 2]) - mx;
            float t3 = fmaf(c, sxl[r + 3], -sbl[r + 3]) - mx;
            float e0 = ex2f(t0), e1 = ex2f(t1), e2 = ex2f(t2), e3 = ex2f(t3);
            den += e0; num = fmaf(e0, sxl[r],     num);
            den += e1; num = fmaf(e1, sxl[r + 1], num);
            den += e2; num = fmaf(e2, sxl[r + 2], num);
            den += e3; num = fmaf(e3, sxl[r + 3], num);
            if (t3 < -T) { r = D; break; }
        }
        for (; r < D; ++r) {
            float t = fmaf(c, sxl[r], -sbl[r]) - mx;
            if (t < -T) break;
            float e = ex2f(t);
            den += e; num = fmaf(e, sxl[r], num);
        }
    }
    g_xs[row * D + i] = num * LN2 / den;
}

// ---------------- kernel 3: split-K GEMM (64x64 tile, KSLICE=32) + fused combine ----
__global__ void __launch_bounds__(256) gemm_fused_kernel(int layer,
                                                         const float* __restrict__ W,
                                                         const float* __restrict__ bias) {
    const float* A = (layer == 0) ? g_xs : g_h1;
    float*       H = (layer == 0) ? g_h1 : g_h2;
    int nt  = blockIdx.x;
    int ks  = blockIdx.y;
    int tid = threadIdx.x;
    int tx  = tid & 15;            // n group (4n)
    int ty  = tid >> 4;            // m group (4m)

    __shared__ __align__(16) float As[2][16][68];   // [k][m] transposed
    __shared__ __align__(16) float Ws[2][16][68];   // [k][n]
    __shared__ int s_last;

    unsigned long long acc[2][4] = {};   // [m-pair][n]

    int r_ld = tid >> 2;           // 0..63
    int k4   = (tid & 3) << 2;     // 0,4,8,12
    const int kbase = ks * KSLICE;

    float4 av = *(const float4*)&A[r_ld * D + kbase + k4];
    float4 wv = *(const float4*)&W[(nt * 64 + r_ld) * D + kbase + k4];
    As[0][k4 + 0][r_ld] = av.x; As[0][k4 + 1][r_ld] = av.y;
    As[0][k4 + 2][r_ld] = av.z; As[0][k4 + 3][r_ld] = av.w;
    Ws[0][k4 + 0][r_ld] = wv.x; Ws[0][k4 + 1][r_ld] = wv.y;
    Ws[0][k4 + 2][r_ld] = wv.z; Ws[0][k4 + 3][r_ld] = wv.w;
    __syncthreads();

#pragma unroll
    for (int c = 0; c < 2; c++) {
        int buf = c & 1;
        float4 av2, wv2;
        if (c < 1) {
            int kb = kbase + 16;
            av2 = *(const float4*)&A[r_ld * D + kb + k4];
            wv2 = *(const float4*)&W[(nt * 64 + r_ld) * D + kb + k4];
        }
#pragma unroll
        for (int k = 0; k < 16; k++) {
            ulonglong2 la = *(const ulonglong2*)&As[buf][k][ty * 4];  // (m0,m1),(m2,m3)
            float4     bv = *(const float4*)&Ws[buf][k][tx * 4];
            unsigned long long b0 = dup2(bv.x);
            unsigned long long b1 = dup2(bv.y);
            unsigned long long b2 = dup2(bv.z);
            unsigned long long b3 = dup2(bv.w);
            ffma2(acc[0][0], la.x, b0); ffma2(acc[1][0], la.y, b0);
            ffma2(acc[0][1], la.x, b1); ffma2(acc[1][1], la.y, b1);
            ffma2(acc[0][2], la.x, b2); ffma2(acc[1][2], la.y, b2);
            ffma2(acc[0][3], la.x, b3); ffma2(acc[1][3], la.y, b3);
        }
        if (c < 1) {
            As[1][k4 + 0][r_ld] = av2.x; As[1][k4 + 1][r_ld] = av2.y;
            As[1][k4 + 2][r_ld] = av2.z; As[1][k4 + 3][r_ld] = av2.w;
            Ws[1][k4 + 0][r_ld] = wv2.x; Ws[1][k4 + 1][r_ld] = wv2.y;
            Ws[1][k4 + 2][r_ld] = wv2.z; Ws[1][k4 + 3][r_ld] = wv2.w;
            __syncthreads();
        }
    }

    // write partials: acc[p][n] lanes = (m = ty*4+2p, m+1)
#pragma unroll
    for (int p = 0; p < 2; p++) {
        unsigned lo0, hi0, lo1, hi1, lo2, hi2, lo3, hi3;
        asm("mov.b64 {%0,%1}, %2;" : "=r"(lo0), "=r"(hi0) : "l"(acc[p][0]));
        asm("mov.b64 {%0,%1}, %2;" : "=r"(lo1), "=r"(hi1) : "l"(acc[p][1]));
        asm("mov.b64 {%0,%1}, %2;" : "=r"(lo2), "=r"(hi2) : "l"(acc[p][2]));
        asm("mov.b64 {%0,%1}, %2;" : "=r"(lo3), "=r"(hi3) : "l"(acc[p][3]));
        int m0 = ty * 4 + 2 * p;
        float4 v0 = make_float4(__uint_as_float(lo0), __uint_as_float(lo1),
                                __uint_as_float(lo2), __uint_as_float(lo3));
        float4 v1 = make_float4(__uint_as_float(hi0), __uint_as_float(hi1),
                                __uint_as_float(hi2), __uint_as_float(hi3));
        *(float4*)&g_part[(ks * BATCH + m0)     * D + nt * 64 + (tx << 2)] = v0;
        *(float4*)&g_part[(ks * BATCH + m0 + 1) * D + nt * 64 + (tx << 2)] = v1;
    }

    // ---- election: last block for this n-tile does the combine ----
    __syncthreads();
    __threadfence();
    if (tid == 0) {
        unsigned old = atomicAdd(&g_cnt[layer][nt], 1u);
        s_last = (old == KSPLIT - 1);
        if (s_last) g_cnt[layer][nt] = 0;
    }
    __syncthreads();
    if (!s_last) return;
    __threadfence();

    // combine: 64 rows x 16 float4-cols of this tile, 4 per thread, 32 partials each
#pragma unroll
    for (int t = 0; t < 4; t++) {
        int idx = t * 256 + tid;
        int m   = idx >> 4;
        int c4  = idx & 15;
        int col = nt * 16 + c4;
        int f4  = m * (D / 4) + col;
        float4 s = ((const float4*)g_part)[(0 * BATCH + m) * (D / 4) + col];
#pragma unroll
        for (int k = 1; k < KSPLIT; k++) {
            float4 v = ((const float4*)g_part)[(k * BATCH + m) * (D / 4) + col];
            s.x += v.x; s.y += v.y; s.z += v.z; s.w += v.w;
        }
        float4 bv = ((const float4*)bias)[col];
        s.x += bv.x; s.y += bv.y; s.z += bv.z; s.w += bv.w;
        s.x = (s.x >= 0.f) ? s.x : 0.01f * s.x;
        s.y = (s.y >= 0.f) ? s.y : 0.01f * s.y;
        s.z = (s.z >= 0.f) ? s.z : 0.01f * s.z;
        s.w = (s.w >= 0.f) ? s.w : 0.01f * s.w;
        ((float4*)H)[f4] = s;
    }
}

// ---------------- kernel 4: final 1024 -> 2 head ----------------
__global__ void __launch_bounds__(256) final_kernel(const float* __restrict__ W3,
                                                    const float* __restrict__ b3,
                                                    float* __restrict__ out) {
    int b   = blockIdx.x;
    int tid = threadIdx.x;
    int c   = tid >> 7;
    int j0  = tid & 127;
    float acc = 0.f;
#pragma unroll
    for (int t = 0; t < 8; t++) {
        int j = j0 + (t << 7);
        acc = fmaf(g_h2[b * D + j], W3[c * D + j], acc);
    }
    __shared__ float red[8];
#pragma unroll
    for (int off = 16; off; off >>= 1)
        acc += __shfl_down_sync(0xffffffffu, acc, off);
    if ((tid & 31) == 0) red[tid >> 5] = acc;
    __syncthreads();
    if (tid < 2) {
        float s = (red[tid * 4] + red[tid * 4 + 1]) +
                  (red[tid * 4 + 2] + red[tid * 4 + 3]);
        out[b * 2 + tid] = s + b3[tid];
    }
}

extern "C" void kernel_launch(void* const* d_in, const int* in_sizes, int n_in,
                              void* d_out, int out_size) {
    const float* x  = (const float*)d_in[0];
    const float* W1 = (const float*)d_in[1];
    const float* b1 = (const float*)d_in[2];
    const float* W2 = (const float*)d_in[3];
    const float* b2 = (const float*)d_in[4];
    const float* W3 = (const float*)d_in[5];
    const float* b3 = (const float*)d_in[6];
    float* out = (float*)d_out;
    (void)in_sizes; (void)n_in; (void)out_size;

    sort_kernel<<<BATCH, D>>>(x);
    softsort_kernel<<<dim3(D / 256, BATCH), 256>>>();
    gemm_fused_kernel<<<dim3(NTILES, KSPLIT), 256>>>(0, W1, b1);
    gemm_fused_kernel<<<dim3(NTILES, KSPLIT), 256>>>(1, W2, b2);
    final_kernel<<<BATCH, 256>>>(W3, b3, out);
}

// round 8
// speedup vs baseline: 1.0394x; 1.0394x over previous
#include <cuda_runtime.h>

#define D      1024
#define BATCH  64
#define KSPLIT 8
#define KSLICE (D / KSPLIT)      // 128
#define NTILES (D / 64)          // 16
#define LOG2E  1.4426950408889634f
#define LN2    0.6931471805599453f

// ---------------- scratch (no allocations allowed) ----------------
__device__ __align__(16) float g_xl[BATCH * D];
__device__ __align__(16) float g_bl[BATCH * D];
__device__ __align__(16) float g_xs[BATCH * D];
__device__ __align__(16) float g_h1[BATCH * D];
__device__ __align__(16) float g_h2[BATCH * D];
__device__ __align__(16) float g_part[2][KSPLIT * BATCH * D];   // 4 MB
__device__ unsigned g_cnt[2][NTILES];
__device__ unsigned g_flag1[NTILES];
__device__ unsigned g_done2;

__device__ __forceinline__ float ex2f(float x) {
    float r;
    asm("ex2.approx.ftz.f32 %0, %1;" : "=f"(r) : "f"(x));
    return r;
}

// ---------------- kernel 1: per-row bitonic sort + prefix-sum Bsum ----------------
__global__ void __launch_bounds__(D) sort_kernel(const float* __restrict__ x) {
    int row = blockIdx.x;
    int tid = threadIdx.x;
    __shared__ __align__(16) float sv[D];
    __shared__ float wsum[32];

    sv[tid] = x[row * D + tid];
    __syncthreads();

    for (int k = 2; k <= D; k <<= 1) {
        for (int j = k >> 1; j > 0; j >>= 1) {
            int ixj = tid ^ j;
            if (ixj > tid) {
                float a = sv[tid], b = sv[ixj];
                bool up = ((tid & k) == 0);
                if ((a > b) == up) { sv[tid] = b; sv[ixj] = a; }
            }
            __syncthreads();
        }
    }

    float v = sv[tid];
    int lane = tid & 31, wid = tid >> 5;
    float p = v;
#pragma unroll
    for (int off = 1; off < 32; off <<= 1) {
        float n = __shfl_up_sync(0xffffffffu, p, off);
        if (lane >= off) p += n;
    }
    if (lane == 31) wsum[wid] = p;
    __syncthreads();
    if (wid == 0) {
        float w = wsum[lane];
#pragma unroll
        for (int off = 1; off < 32; off <<= 1) {
            float n = __shfl_up_sync(0xffffffffu, w, off);
            if (lane >= off) w += n;
        }
        wsum[lane] = w;
    }
    __syncthreads();
    float S    = wsum[31];
    float pinc = p + (wid ? wsum[wid - 1] : 0.f);
    float bs   = (float)(2 * tid - D) * v + S - 2.f * (pinc - v);
    g_xl[row * D + tid] = v * LOG2E;
    g_bl[row * D + tid] = bs * LOG2E;
}

// ---------------- kernel 2: windowed soft-sort, unroll-4 ----------------
__global__ void __launch_bounds__(256) softsort_kernel() {
    int row = blockIdx.y;
    int i   = blockIdx.x * blockDim.x + threadIdx.x;
    __shared__ __align__(16) float sxl[D];
    __shared__ __align__(16) float sbl[D];
    ((float4*)sxl)[threadIdx.x] = ((const float4*)(g_xl + row * D))[threadIdx.x];
    ((float4*)sbl)[threadIdx.x] = ((const float4*)(g_bl + row * D))[threadIdx.x];
    __syncthreads();

    float c  = (float)(D - 1 - 2 * i);
    int   rm = D - 1 - i;
    float mx = fmaf(c, sxl[rm], -sbl[rm]);
    float num = sxl[rm], den = 1.f;
    const float T = 22.f;

    {
        int r = rm - 1;
        for (; r >= 3; r -= 4) {
            float t0 = fmaf(c, sxl[r],     -sbl[r])     - mx;
            float t1 = fmaf(c, sxl[r - 1], -sbl[r - 1]) - mx;
            float t2 = fmaf(c, sxl[r - 2], -sbl[r - 2]) - mx;
            float t3 = fmaf(c, sxl[r - 3], -sbl[r - 3]) - mx;
            float e0 = ex2f(t0), e1 = ex2f(t1), e2 = ex2f(t2), e3 = ex2f(t3);
            den += e0; num = fmaf(e0, sxl[r],     num);
            den += e1; num = fmaf(e1, sxl[r - 1], num);
            den += e2; num = fmaf(e2, sxl[r - 2], num);
            den += e3; num = fmaf(e3, sxl[r - 3], num);
            if (t3 < -T) { r = -1; break; }
        }
        for (; r >= 0; --r) {
            float t = fmaf(c, sxl[r], -sbl[r]) - mx;
            if (t < -T) break;
            float e = ex2f(t);
            den += e; num = fmaf(e, sxl[r], num);
        }
    }
    {
        int r = rm + 1;
        for (; r < D - 3; r += 4) {
            float t0 = fmaf(c, sxl[r],     -sbl[r])     - mx;
            float t1 = fmaf(c, sxl[r + 1], -sbl[r + 1]) - mx;
            float t2 = fmaf(c, sxl[r + 2], -sbl[r + 2]) - mx;
            float t3 = fmaf(c, sxl[r + 3], -sbl[r + 3]) - mx;
            float e0 = ex2f(t0), e1 = ex2f(t1), e2 = ex2f(t2), e3 = ex2f(t3);
            den += e0; num = fmaf(e0, sxl[r],     num);
            den += e1; num = fmaf(e1, sxl[r + 1], num);
            den += e2; num = fmaf(e2, sxl[r + 2], num);
            den += e3; num = fmaf(e3, sxl[r + 3], num);
            if (t3 < -T) { r = D; break; }
        }
        for (; r < D; ++r) {
            float t = fmaf(c, sxl[r], -sbl[r]) - mx;
            if (t < -T) break;
            float e = ex2f(t);
            den += e; num = fmaf(e, sxl[r], num);
        }
    }
    g_xs[row * D + i] = num * LN2 / den;
}

// ---------------- GEMM building blocks (R3-proven mainloop) ----------------
__device__ __forceinline__ void mma_slice(const float* __restrict__ A,
                                          const float* __restrict__ W,
                                          int nt, int ks, int tid,
                                          float (&As)[16][68], float (&Ws)[16][68],
                                          float (&acc)[4][4]) {
    int tx = tid & 15;
    int ty = tid >> 4;
    int m_ld = tid >> 2;
    int k4   = (tid & 3) << 2;
    const int kbase0 = ks * KSLICE;

    for (int kk = 0; kk < KSLICE; kk += 16) {
        int kb = kbase0 + kk;
        float4 av = *(const float4*)&A[m_ld * D + kb + k4];
        float4 wv = *(const float4*)&W[(nt * 64 + m_ld) * D + kb + k4];
        __syncthreads();
        As[k4 + 0][m_ld] = av.x; As[k4 + 1][m_ld] = av.y;
        As[k4 + 2][m_ld] = av.z; As[k4 + 3][m_ld] = av.w;
        Ws[k4 + 0][m_ld] = wv.x; Ws[k4 + 1][m_ld] = wv.y;
        Ws[k4 + 2][m_ld] = wv.z; Ws[k4 + 3][m_ld] = wv.w;
        __syncthreads();
#pragma unroll
        for (int k = 0; k < 16; k++) {
            float4 a = *(const float4*)&As[k][ty << 2];
            float4 b = *(const float4*)&Ws[k][tx << 2];
            acc[0][0] = fmaf(a.x, b.x, acc[0][0]);
            acc[0][1] = fmaf(a.x, b.y, acc[0][1]);
            acc[0][2] = fmaf(a.x, b.z, acc[0][2]);
            acc[0][3] = fmaf(a.x, b.w, acc[0][3]);
            acc[1][0] = fmaf(a.y, b.x, acc[1][0]);
            acc[1][1] = fmaf(a.y, b.y, acc[1][1]);
            acc[1][2] = fmaf(a.y, b.z, acc[1][2]);
            acc[1][3] = fmaf(a.y, b.w, acc[1][3]);
            acc[2][0] = fmaf(a.z, b.x, acc[2][0]);
            acc[2][1] = fmaf(a.z, b.y, acc[2][1]);
            acc[2][2] = fmaf(a.z, b.z, acc[2][2]);
            acc[2][3] = fmaf(a.z, b.w, acc[2][3]);
            acc[3][0] = fmaf(a.w, b.x, acc[3][0]);
            acc[3][1] = fmaf(a.w, b.y, acc[3][1]);
            acc[3][2] = fmaf(a.w, b.z, acc[3][2]);
            acc[3][3] = fmaf(a.w, b.w, acc[3][3]);
        }
    }
}

__device__ __forceinline__ void write_partials(float* __restrict__ part,
                                               int nt, int ks, int tid,
                                               float (&acc)[4][4]) {
    int tx = tid & 15;
    int ty = tid >> 4;
#pragma unroll
    for (int i = 0; i < 4; i++) {
        int m = (ty << 2) + i;
        float4 v = make_float4(acc[i][0], acc[i][1], acc[i][2], acc[i][3]);
        *(float4*)&part[(ks * BATCH + m) * D + nt * 64 + (tx << 2)] = v;
    }
}

__device__ __forceinline__ void combine_tile(const float* __restrict__ part,
                                             const float* __restrict__ bias,
                                             float* __restrict__ H,
                                             int nt, int tid) {
#pragma unroll
    for (int t = 0; t < 4; t++) {
        int idx = t * 256 + tid;
        int m   = idx >> 4;
        int c4  = idx & 15;
        int col = nt * 16 + c4;
        float4 s = ((const float4*)part)[(0 * BATCH + m) * (D / 4) + col];
#pragma unroll
        for (int k = 1; k < KSPLIT; k++) {
            float4 v = ((const float4*)part)[(k * BATCH + m) * (D / 4) + col];
            s.x += v.x; s.y += v.y; s.z += v.z; s.w += v.w;
        }
        float4 bv = ((const float4*)bias)[col];
        s.x += bv.x; s.y += bv.y; s.z += bv.z; s.w += bv.w;
        s.x = (s.x >= 0.f) ? s.x : 0.01f * s.x;
        s.y = (s.y >= 0.f) ? s.y : 0.01f * s.y;
        s.z = (s.z >= 0.f) ? s.z : 0.01f * s.z;
        s.w = (s.w >= 0.f) ? s.w : 0.01f * s.w;
        ((float4*)H)[m * (D / 4) + col] = s;
    }
}

// ---------------- kernel 3: fused MLP (layer1 + layer2 + head), 128 blocks ------
__global__ void __launch_bounds__(256) mlp_kernel(const float* __restrict__ W1,
                                                  const float* __restrict__ b1,
                                                  const float* __restrict__ W2,
                                                  const float* __restrict__ b2,
                                                  const float* __restrict__ W3,
                                                  const float* __restrict__ b3,
                                                  float* __restrict__ out) {
    int nt  = blockIdx.x;
    int ks  = blockIdx.y;
    int tid = threadIdx.x;

    __shared__ __align__(16) float As[16][68];
    __shared__ __align__(16) float Ws[16][68];
    __shared__ int s_flag;

    // ======== layer 1 ========
    {
        float acc[4][4] = {};
        mma_slice(g_xs, W1, nt, ks, tid, As, Ws, acc);
        write_partials(g_part[0], nt, ks, tid, acc);
        __syncthreads();
        __threadfence();
        if (tid == 0) {
            unsigned old = atomicAdd(&g_cnt[0][nt], 1u);
            s_flag = (old == KSPLIT - 1);
            if (s_flag) g_cnt[0][nt] = 0;
        }
        __syncthreads();
        if (s_flag) {
            __threadfence();
            combine_tile(g_part[0], b1, g_h1, nt, tid);
            __syncthreads();
            __threadfence();
            if (tid == 0) atomicExch(&g_flag1[nt], 1u);
        }
    }

    // ======== wait for the two h1 tiles covering this block's k-slice ========
    {
        int t0 = 2 * ks, t1 = 2 * ks + 1;
        if (tid == 0) {
            while (atomicAdd(&g_flag1[t0], 0u) == 0u) __nanosleep(64);
            while (atomicAdd(&g_flag1[t1], 0u) == 0u) __nanosleep(64);
        }
        __syncthreads();
        __threadfence();
    }

    // ======== layer 2 ========
    {
        float acc[4][4] = {};
        mma_slice(g_h1, W2, nt, ks, tid, As, Ws, acc);
        write_partials(g_part[1], nt, ks, tid, acc);
        __syncthreads();
        __threadfence();
        if (tid == 0) {
            unsigned old = atomicAdd(&g_cnt[1][nt], 1u);
            s_flag = (old == KSPLIT - 1);
            if (s_flag) g_cnt[1][nt] = 0;
        }
        __syncthreads();
        if (!s_flag) return;
        __threadfence();
        combine_tile(g_part[1], b2, g_h2, nt, tid);
        __syncthreads();
        __threadfence();
        if (tid == 0) {
            unsigned old = atomicAdd(&g_done2, 1u);
            s_flag = (old == NTILES - 1);
        }
        __syncthreads();
        if (!s_flag) return;
        __threadfence();
    }

    // ======== final head: out[b*2+c] = h2[b] . W3[c] + b3[c] ========
    {
        int wo   = tid >> 5;        // warp 0..7
        int lane = tid & 31;
#pragma unroll
        for (int o = wo; o < 2 * BATCH; o += 8) {
            int b  = o >> 1;
            int ch = o & 1;
            const float4* h = (const float4*)&g_h2[b * D];
            const float4* w = (const float4*)&W3[ch * D];
            float s = 0.f;
#pragma unroll
            for (int j = 0; j < 8; j++) {
                float4 hv = h[lane + 32 * j];
                float4 wv = w[lane + 32 * j];
                s = fmaf(hv.x, wv.x, s); s = fmaf(hv.y, wv.y, s);
                s = fmaf(hv.z, wv.z, s); s = fmaf(hv.w, wv.w, s);
            }
#pragma unroll
            for (int off = 16; off; off >>= 1)
                s += __shfl_down_sync(0xffffffffu, s, off);
            if (lane == 0) out[o] = s + b3[ch];
        }
        // reset flags/counters for the next graph replay (this block is last)
        __syncthreads();
        if (tid < NTILES) g_flag1[tid] = 0u;
        if (tid == 0)     g_done2 = 0u;
    }
}

extern "C" void kernel_launch(void* const* d_in, const int* in_sizes, int n_in,
                              void* d_out, int out_size) {
    const float* x  = (const float*)d_in[0];
    const float* W1 = (const float*)d_in[1];
    const float* b1 = (const float*)d_in[2];
    const float* W2 = (const float*)d_in[3];
    const float* b2 = (const float*)d_in[4];
    const float* W3 = (const float*)d_in[5];
    const float* b3 = (const float*)d_in[6];
    float* out = (float*)d_out;
    (void)in_sizes; (void)n_in; (void)out_size;

    sort_kernel<<<BATCH, D>>>(x);
    softsort_kernel<<<dim3(D / 256, BATCH), 256>>>();
    mlp_kernel<<<dim3(NTILES, KSPLIT), 256>>>(W1, b1, W2, b2, W3, b3, out);
}

// round 9
// speedup vs baseline: 1.3715x; 1.3195x over previous
#include <cuda_runtime.h>

#define D      1024
#define BATCH  64
#define KSPLIT 8
#define NTILES (D / 64)
#define LOG2E  1.4426950408889634f
#define LN2    0.6931471805599453f

// ---------------- scratch (no allocations allowed) ----------------
__device__ __align__(16) float g_xl[BATCH * D];
__device__ __align__(16) float g_bl[BATCH * D];
__device__ __align__(16) float g_xs[BATCH * D];
__device__ __align__(16) float g_h1[BATCH * D];
__device__ __align__(16) float g_h2[BATCH * D];
__device__ __align__(16) float g_part[KSPLIT * BATCH * D];
__device__ unsigned g_cnt[2][NTILES];

__device__ __forceinline__ float ex2f(float x) {
    float r;
    asm("ex2.approx.ftz.f32 %0, %1;" : "=f"(r) : "f"(x));
    return r;
}

__device__ __forceinline__ void cexch(float& a, float& b, bool up) {
    if ((a > b) == up) { float t = a; a = b; b = t; }
}

// ---------------- kernel 1: register-blocked bitonic sort + Bsum ----------------
// 256 threads, 4 elements/thread. j<=2 phases in registers; j>=4 via smem float4.
__global__ void __launch_bounds__(256) sort_kernel(const float* __restrict__ x) {
    int row = blockIdx.x;
    int tid = threadIdx.x;
    __shared__ __align__(16) float sv[D];
    __shared__ float wsum[8];
    float4* sv4 = (float4*)sv;

    float4 q = ((const float4*)(x + row * D))[tid];

    // k=2 (j=1): (x,y) asc, (z,w) desc
    cexch(q.x, q.y, true);
    cexch(q.z, q.w, false);
    // k=4 (j=2,1): up = ((tid&1)==0)
    {
        bool up = (tid & 1) == 0;
        cexch(q.x, q.z, up); cexch(q.y, q.w, up);
        cexch(q.x, q.y, up); cexch(q.z, q.w, up);
    }
    sv4[tid] = q;

    for (int k = 8; k <= D; k <<= 1) {
        bool upk = (tid & (k >> 2)) == 0;
        for (int j = k >> 1; j >= 4; j >>= 1) {
            __syncthreads();
            int pj = j >> 2;
            if ((tid & pj) == 0) {
                float4 a = sv4[tid];
                float4 b = sv4[tid ^ pj];
                cexch(a.x, b.x, upk); cexch(a.y, b.y, upk);
                cexch(a.z, b.z, upk); cexch(a.w, b.w, upk);
                sv4[tid] = a;
                sv4[tid ^ pj] = b;
            }
        }
        __syncthreads();
        q = sv4[tid];
        cexch(q.x, q.z, upk); cexch(q.y, q.w, upk);
        cexch(q.x, q.y, upk); cexch(q.z, q.w, upk);
        sv4[tid] = q;
    }
    // q now holds the sorted values at ranks 4tid..4tid+3 (ascending)

    // prefix sums: local inclusive, warp scan over thread-sums, block scan over warps
    float l0 = q.x;
    float l1 = l0 + q.y;
    float l2 = l1 + q.z;
    float l3 = l2 + q.w;
    int lane = tid & 31, wid = tid >> 5;
    float p = l3;
#pragma unroll
    for (int off = 1; off < 32; off <<= 1) {
        float n = __shfl_up_sync(0xffffffffu, p, off);
        if (lane >= off) p += n;
    }
    if (lane == 31) wsum[wid] = p;
    __syncthreads();
    float wbase = 0.f, S = 0.f;
#pragma unroll
    for (int w = 0; w < 8; w++) {
        float v = wsum[w];
        if (w < wid) wbase += v;
        S += v;
    }
    float base = wbase + (p - l3);   // exclusive prefix before this thread's 4

    float4 pinc = make_float4(base + l0, base + l1, base + l2, base + l3);
    int r0 = tid * 4;
    float4 bs;
    bs.x = (float)(2 * (r0 + 0) - D) * q.x + S - 2.f * (pinc.x - q.x);
    bs.y = (float)(2 * (r0 + 1) - D) * q.y + S - 2.f * (pinc.y - q.y);
    bs.z = (float)(2 * (r0 + 2) - D) * q.z + S - 2.f * (pinc.z - q.z);
    bs.w = (float)(2 * (r0 + 3) - D) * q.w + S - 2.f * (pinc.w - q.w);

    float4 xl = make_float4(q.x * LOG2E, q.y * LOG2E, q.z * LOG2E, q.w * LOG2E);
    float4 bl = make_float4(bs.x * LOG2E, bs.y * LOG2E, bs.z * LOG2E, bs.w * LOG2E);
    ((float4*)(g_xl + row * D))[tid] = xl;
    ((float4*)(g_bl + row * D))[tid] = bl;
}

// ---------------- kernel 2: windowed soft-sort, unroll-4 ----------------
__global__ void __launch_bounds__(256) softsort_kernel() {
    int row = blockIdx.y;
    int i   = blockIdx.x * blockDim.x + threadIdx.x;
    __shared__ __align__(16) float sxl[D];
    __shared__ __align__(16) float sbl[D];
    ((float4*)sxl)[threadIdx.x] = ((const float4*)(g_xl + row * D))[threadIdx.x];
    ((float4*)sbl)[threadIdx.x] = ((const float4*)(g_bl + row * D))[threadIdx.x];
    __syncthreads();

    float c  = (float)(D - 1 - 2 * i);
    int   rm = D - 1 - i;
    float mx = fmaf(c, sxl[rm], -sbl[rm]);
    float num = sxl[rm], den = 1.f;
    const float T = 22.f;

    {
        int r = rm - 1;
        for (; r >= 3; r -= 4) {
            float t0 = fmaf(c, sxl[r],     -sbl[r])     - mx;
            float t1 = fmaf(c, sxl[r - 1], -sbl[r - 1]) - mx;
            float t2 = fmaf(c, sxl[r - 2], -sbl[r - 2]) - mx;
            float t3 = fmaf(c, sxl[r - 3], -sbl[r - 3]) - mx;
            float e0 = ex2f(t0), e1 = ex2f(t1), e2 = ex2f(t2), e3 = ex2f(t3);
            den += e0; num = fmaf(e0, sxl[r],     num);
            den += e1; num = fmaf(e1, sxl[r - 1], num);
            den += e2; num = fmaf(e2, sxl[r - 2], num);
            den += e3; num = fmaf(e3, sxl[r - 3], num);
            if (t3 < -T) { r = -1; break; }
        }
        for (; r >= 0; --r) {
            float t = fmaf(c, sxl[r], -sbl[r]) - mx;
            if (t < -T) break;
            float e = ex2f(t);
            den += e; num = fmaf(e, sxl[r], num);
        }
    }
    {
        int r = rm + 1;
        for (; r < D - 3; r += 4) {
            float t0 = fmaf(c, sxl[r],     -sbl[r])     - mx;
            float t1 = fmaf(c, sxl[r + 1], -sbl[r + 1]) - mx;
            float t2 = fmaf(c, sxl[r + 2], -sbl[r + 2]) - mx;
            float t3 = fmaf(c, sxl[r + 3], -sbl[r + 3]) - mx;
            float e0 = ex2f(t0), e1 = ex2f(t1), e2 = ex2f(t2), e3 = ex2f(t3);
            den += e0; num = fmaf(e0, sxl[r],     num);
            den += e1; num = fmaf(e1, sxl[r + 1], num);
            den += e2; num = fmaf(e2, sxl[r + 2], num);
            den += e3; num = fmaf(e3, sxl[r + 3], num);
            if (t3 < -T) { r = D; break; }
        }
        for (; r < D; ++r) {
            float t = fmaf(c, sxl[r], -sbl[r]) - mx;
            if (t < -T) break;
            float e = ex2f(t);
            den += e; num = fmaf(e, sxl[r], num);
        }
    }
    g_xs[row * D + i] = num * LN2 / den;
}

// ---------------- kernel 3: split-K GEMM + fused last-block combine (R3) --------
__global__ void __launch_bounds__(256) gemm_fused_kernel(int layer,
                                                         const float* __restrict__ W,
                                                         const float* __restrict__ bias) {
    const float* A = (layer == 0) ? g_xs : g_h1;
    float*       H = (layer == 0) ? g_h1 : g_h2;
    int nt  = blockIdx.x;
    int ks  = blockIdx.y;
    int tid = threadIdx.x;
    int tx  = tid & 15;
    int ty  = tid >> 4;
    __shared__ __align__(16) float As[16][68];
    __shared__ __align__(16) float Ws[16][68];
    __shared__ int s_last;
    float acc[4][4];
#pragma unroll
    for (int i = 0; i < 4; i++)
#pragma unroll
        for (int j = 0; j < 4; j++) acc[i][j] = 0.f;

    int m_ld = tid >> 2;
    int k4   = (tid & 3) << 2;
    const int kbase0 = ks * (D / KSPLIT);

    for (int kk = 0; kk < D / KSPLIT; kk += 16) {
        int kb = kbase0 + kk;
        float4 av = *(const float4*)&A[m_ld * D + kb + k4];
        float4 wv = *(const float4*)&W[(nt * 64 + m_ld) * D + kb + k4];
        __syncthreads();
        As[k4 + 0][m_ld] = av.x; As[k4 + 1][m_ld] = av.y;
        As[k4 + 2][m_ld] = av.z; As[k4 + 3][m_ld] = av.w;
        Ws[k4 + 0][m_ld] = wv.x; Ws[k4 + 1][m_ld] = wv.y;
        Ws[k4 + 2][m_ld] = wv.z; Ws[k4 + 3][m_ld] = wv.w;
        __syncthreads();
#pragma unroll
        for (int k = 0; k < 16; k++) {
            float4 a = *(const float4*)&As[k][ty << 2];
            float4 b = *(const float4*)&Ws[k][tx << 2];
            acc[0][0] = fmaf(a.x, b.x, acc[0][0]);
            acc[0][1] = fmaf(a.x, b.y, acc[0][1]);
            acc[0][2] = fmaf(a.x, b.z, acc[0][2]);
            acc[0][3] = fmaf(a.x, b.w, acc[0][3]);
            acc[1][0] = fmaf(a.y, b.x, acc[1][0]);
            acc[1][1] = fmaf(a.y, b.y, acc[1][1]);
            acc[1][2] = fmaf(a.y, b.z, acc[1][2]);
            acc[1][3] = fmaf(a.y, b.w, acc[1][3]);
            acc[2][0] = fmaf(a.z, b.x, acc[2][0]);
            acc[2][1] = fmaf(a.z, b.y, acc[2][1]);
            acc[2][2] = fmaf(a.z, b.z, acc[2][2]);
            acc[2][3] = fmaf(a.z, b.w, acc[2][3]);
            acc[3][0] = fmaf(a.w, b.x, acc[3][0]);
            acc[3][1] = fmaf(a.w, b.y, acc[3][1]);
            acc[3][2] = fmaf(a.w, b.z, acc[3][2]);
            acc[3][3] = fmaf(a.w, b.w, acc[3][3]);
        }
    }
#pragma unroll
    for (int i = 0; i < 4; i++) {
        int m = (ty << 2) + i;
        float4 v = make_float4(acc[i][0], acc[i][1], acc[i][2], acc[i][3]);
        *(float4*)&g_part[(ks * BATCH + m) * D + nt * 64 + (tx << 2)] = v;
    }

    __syncthreads();
    __threadfence();
    if (tid == 0) {
        unsigned old = atomicAdd(&g_cnt[layer][nt], 1u);
        s_last = (old == KSPLIT - 1);
        if (s_last) g_cnt[layer][nt] = 0;
    }
    __syncthreads();
    if (!s_last) return;
    __threadfence();

#pragma unroll
    for (int t = 0; t < 4; t++) {
        int idx = t * 256 + tid;
        int m   = idx >> 4;
        int c4  = idx & 15;
        int f4  = m * (D / 4) + nt * 16 + c4;
        float4 s = ((const float4*)g_part)[(0 * BATCH + m) * (D / 4) + nt * 16 + c4];
#pragma unroll
        for (int k = 1; k < KSPLIT; k++) {
            float4 v = ((const float4*)g_part)[(k * BATCH + m) * (D / 4) + nt * 16 + c4];
            s.x += v.x; s.y += v.y; s.z += v.z; s.w += v.w;
        }
        float4 bv = ((const float4*)bias)[nt * 16 + c4];
        s.x += bv.x; s.y += bv.y; s.z += bv.z; s.w += bv.w;
        s.x = (s.x >= 0.f) ? s.x : 0.01f * s.x;
        s.y = (s.y >= 0.f) ? s.y : 0.01f * s.y;
        s.z = (s.z >= 0.f) ? s.z : 0.01f * s.z;
        s.w = (s.w >= 0.f) ? s.w : 0.01f * s.w;
        ((float4*)H)[f4] = s;
    }
}

// ---------------- kernel 4: final 1024 -> 2 head ----------------
__global__ void __launch_bounds__(256) final_kernel(const float* __restrict__ W3,
                                                    const float* __restrict__ b3,
                                                    float* __restrict__ out) {
    int b   = blockIdx.x;
    int tid = threadIdx.x;
    int c   = tid >> 7;
    int j0  = tid & 127;
    float acc = 0.f;
#pragma unroll
    for (int t = 0; t < 8; t++) {
        int j = j0 + (t << 7);
        acc = fmaf(g_h2[b * D + j], W3[c * D + j], acc);
    }
    __shared__ float red[8];
#pragma unroll
    for (int off = 16; off; off >>= 1)
        acc += __shfl_down_sync(0xffffffffu, acc, off);
    if ((tid & 31) == 0) red[tid >> 5] = acc;
    __syncthreads();
    if (tid < 2) {
        float s = (red[tid * 4] + red[tid * 4 + 1]) +
                  (red[tid * 4 + 2] + red[tid * 4 + 3]);
        out[b * 2 + tid] = s + b3[tid];
    }
}

extern "C" void kernel_launch(void* const* d_in, const int* in_sizes, int n_in,
                              void* d_out, int out_size) {
    const float* x  = (const float*)d_in[0];
    const float* W1 = (const float*)d_in[1];
    const float* b1 = (const float*)d_in[2];
    const float* W2 = (const float*)d_in[3];
    const float* b2 = (const float*)d_in[4];
    const float* W3 = (const float*)d_in[5];
    const float* b3 = (const float*)d_in[6];
    float* out = (float*)d_out;
    (void)in_sizes; (void)n_in; (void)out_size;

    sort_kernel<<<BATCH, 256>>>(x);
    softsort_kernel<<<dim3(D / 256, BATCH), 256>>>();
    gemm_fused_kernel<<<dim3(NTILES, KSPLIT), 256>>>(0, W1, b1);
    gemm_fused_kernel<<<dim3(NTILES, KSPLIT), 256>>>(1, W2, b2);
    final_kernel<<<BATCH, 256>>>(W3, b3, out);
}